// round 6
// baseline (speedup 1.0000x reference)
#include <cuda_runtime.h>
#include <cuda_bf16.h>
#include <math.h>
#include <cstdint>

#define B_SZ 512
#define K_SZ 32
#define D_SZ 768
#define ROW_BYTES (D_SZ * 4)        // 3072
#define N_SENSES 200000
#define NEG_INF -1e30f

#define WARPS_PER_CTA 8             // 8 candidates of the SAME sample per CTA
#define CTA_THREADS (WARPS_PER_CTA * 32)
#define GRID_CTAS ((B_SZ * K_SZ) / WARPS_PER_CTA)   // 2048

// Global scratch. Counters use atomicInc wrap -> self-reset each full launch,
// deterministic under graph replay.
__device__ float    g_logits[B_SZ * K_SZ];
__device__ float    g_nll[B_SZ];
__device__ unsigned g_cnt[B_SZ];
__device__ unsigned g_done = 0;

__device__ __forceinline__ uint32_t smem_u32(const void* p) {
    return (uint32_t)__cvta_generic_to_shared(p);
}

__global__ __launch_bounds__(CTA_THREADS)
void cbert_bulk_kernel(const float* __restrict__ reps,
                       const float* __restrict__ weight,
                       const float* __restrict__ bias,
                       const int* __restrict__ sense_ids,
                       const int* __restrict__ target_ids,
                       float* __restrict__ out, int out_size) {
    __shared__ __align__(128) float s_w[WARPS_PER_CTA][D_SZ];   // 24 KB
    __shared__ __align__(128) float s_reps[D_SZ];               // 3 KB
    __shared__ __align__(8) unsigned long long s_mbar[WARPS_PER_CTA];

    const int tid  = threadIdx.x;
    const int lane = tid & 31;
    const int warp = tid >> 5;
    const int gwarp = blockIdx.x * WARPS_PER_CTA + warp;
    const int b = gwarp >> 5;          // same b for the whole CTA (8 | 32)
    const int k = gwarp & 31;

    const int id = sense_ids[b * K_SZ + k];
    const bool valid = (id >= 0 && id < N_SENSES);
    const uint32_t mbar = smem_u32(&s_mbar[warp]);

    // Per-warp mbarrier init, then async-proxy fence, then issue bulk copy.
    if (lane == 0) {
        asm volatile("mbarrier.init.shared.b64 [%0], %1;"
                     :: "r"(mbar), "r"(1u) : "memory");
    }
    __syncwarp();
    asm volatile("fence.proxy.async.shared::cta;" ::: "memory");

    if (valid && lane == 0) {
        asm volatile("mbarrier.arrive.expect_tx.shared.b64 _, [%0], %1;"
                     :: "r"(mbar), "r"((uint32_t)ROW_BYTES) : "memory");
        const void* src = (const void*)(weight + (size_t)id * D_SZ);
        asm volatile(
            "cp.async.bulk.shared::cta.global.mbarrier::complete_tx::bytes "
            "[%0], [%1], %2, [%3];"
            :: "r"(smem_u32(&s_w[warp][0])), "l"(src),
               "r"((uint32_t)ROW_BYTES), "r"(mbar) : "memory");
    }

    // Stage reps[b] cooperatively while the bulk copies fly (192 float4).
    {
        const float4* src = reinterpret_cast<const float4*>(reps + (size_t)b * D_SZ);
        float4* dst = reinterpret_cast<float4*>(s_reps);
        if (tid < D_SZ / 4) dst[tid] = src[tid];
    }
    __syncthreads();   // s_reps visible to all warps

    float logit = NEG_INF;
    if (valid) {
        // Wait for this warp's row (all lanes poll; acquire orders later LDS).
        uint32_t done;
        do {
            asm volatile(
                "{\n\t.reg .pred p;\n\t"
                "mbarrier.try_wait.parity.acquire.cta.shared::cta.b64 p, [%1], %2, 0x989680;\n\t"
                "selp.b32 %0, 1, 0, p;\n\t}"
                : "=r"(done) : "r"(mbar), "r"(0u) : "memory");
        } while (!done);

        const float4* w4 = reinterpret_cast<const float4*>(&s_w[warp][0]);
        const float4* r4 = reinterpret_cast<const float4*>(s_reps);
        float acc = 0.f;
        #pragma unroll
        for (int j = 0; j < 6; ++j) {
            const int i = lane + 32 * j;
            float4 w = w4[i];
            float4 r = r4[i];
            acc = fmaf(w.x, r.x, acc);
            acc = fmaf(w.y, r.y, acc);
            acc = fmaf(w.z, r.z, acc);
            acc = fmaf(w.w, r.w, acc);
        }
        #pragma unroll
        for (int off = 16; off > 0; off >>= 1)
            acc += __shfl_down_sync(0xFFFFFFFFu, acc, off);
        if (lane == 0) logit = acc + bias[id];
    }

    // ---- Phase 2 trigger: publish logit, count arrivals for sample b ----
    unsigned old = 0;
    if (lane == 0) {
        __stcg(&g_logits[b * K_SZ + k], logit);
        __threadfence();
        old = atomicInc(&g_cnt[b], K_SZ - 1);
    }
    old = __shfl_sync(0xFFFFFFFFu, old, 0);
    if (old != K_SZ - 1) return;

    // ---- Phase 2: last warp for sample b does the 32-wide softmax ----
    __threadfence();
    float v = __ldcg(&g_logits[b * K_SZ + lane]);

    float mval = v; int midx = lane;
    #pragma unroll
    for (int off = 16; off > 0; off >>= 1) {
        float ov = __shfl_down_sync(0xFFFFFFFFu, mval, off);
        int   oi = __shfl_down_sync(0xFFFFFFFFu, midx, off);
        if (ov > mval || (ov == mval && oi < midx)) { mval = ov; midx = oi; }
    }
    mval = __shfl_sync(0xFFFFFFFFu, mval, 0);
    midx = __shfl_sync(0xFFFFFFFFu, midx, 0);

    float e = expf(v - mval);
    #pragma unroll
    for (int off = 16; off > 0; off >>= 1)
        e += __shfl_down_sync(0xFFFFFFFFu, e, off);
    float sumexp = __shfl_sync(0xFFFFFFFFu, e, 0);

    const int tgt = target_ids[b];
    float tlogit = __shfl_sync(0xFFFFFFFFu, v, tgt & 31);

    unsigned done2 = 0;
    if (lane == 0) {
        float nll = -(tlogit - mval - logf(sumexp));
        __stcg(&g_nll[b], nll);
        if (1 + b < out_size) out[1 + b] = (midx == tgt) ? 1.0f : 0.0f;
        __threadfence();
        done2 = atomicInc(&g_done, B_SZ - 1);
    }
    done2 = __shfl_sync(0xFFFFFFFFu, done2, 0);
    if (done2 != B_SZ - 1) return;

    // ---- Phase 3: deterministic fixed-order mean of the 512 NLLs ----
    __threadfence();
    float acc = 0.f;
    #pragma unroll
    for (int i = 0; i < B_SZ / 32; ++i)
        acc += __ldcg(&g_nll[lane + 32 * i]);
    #pragma unroll
    for (int off = 16; off > 0; off >>= 1)
        acc += __shfl_down_sync(0xFFFFFFFFu, acc, off);
    if (lane == 0 && out_size > 0) out[0] = acc / (float)B_SZ;
}

extern "C" void kernel_launch(void* const* d_in, const int* in_sizes, int n_in,
                              void* d_out, int out_size) {
    const float* reps = (const float*)d_in[0];
    const float* weight = (const float*)d_in[1];
    const float* bias = (const float*)d_in[2];
    const int* sense_ids = (const int*)d_in[3];
    const int* target_ids = (const int*)d_in[4];
    float* out = (float*)d_out;

    cbert_bulk_kernel<<<GRID_CTAS, CTA_THREADS>>>(reps, weight, bias,
                                                  sense_ids, target_ids,
                                                  out, out_size);
}